// round 5
// baseline (speedup 1.0000x reference)
#include <cuda_runtime.h>
#include <cstdint>

#define HIDDEN 1024
#define NCOLS 1858
#define NROWS_PM 4288
#define MAXB 2048

// ---------------- scratch (device globals: allocation-free) ----------------
__device__ float g_T[(size_t)MAXB * 64 * HIDDEN];   // T = HS @ M
__device__ float g_M[HIDDEN * HIDDEN];              // g_M[n][k] = M[k][n], M = Wq^T Wk
__device__ float g_Weff[3 * HIDDEN];
__device__ float g_PO[MAXB * 24];
__device__ int   g_cnt[NCOLS];
__device__ int   g_rows[NCOLS * 16];
__device__ int   g_cnt4[4 * NCOLS];
__device__ int   g_rows4[4 * NCOLS * 16];

// ---------------- PTX helpers (arch-agnostic: sm_80+ only) -----------------
__device__ __forceinline__ uint32_t smem_u32(const void* p) {
    uint32_t a;
    asm("{ .reg .u64 t; cvta.to.shared.u64 t, %1; cvt.u32.u64 %0, t; }" : "=r"(a) : "l"(p));
    return a;
}
__device__ __forceinline__ void cp_async16(uint32_t s, const void* g) {
    asm volatile("cp.async.cg.shared.global [%0], [%1], 16;" :: "r"(s), "l"(g));
}
#define CP_COMMIT() asm volatile("cp.async.commit_group;" ::: "memory")
#define CP_WAIT1() asm volatile("cp.async.wait_group 1;" ::: "memory")
#define CP_WAIT0() asm volatile("cp.async.wait_group 0;" ::: "memory")

__device__ __forceinline__ uint32_t f2tf32(float x) {
    uint32_t r;
    asm("cvt.rna.tf32.f32 %0, %1;" : "=r"(r) : "f"(x));
    return r;
}
__device__ __forceinline__ void mma_tf32(float* c, const uint32_t* a, const uint32_t* b) {
    asm volatile(
        "mma.sync.aligned.m16n8k8.row.col.f32.tf32.tf32.f32 "
        "{%0,%1,%2,%3}, {%4,%5,%6,%7}, {%8,%9}, {%0,%1,%2,%3};"
        : "+f"(c[0]), "+f"(c[1]), "+f"(c[2]), "+f"(c[3])
        : "r"(a[0]), "r"(a[1]), "r"(a[2]), "r"(a[3]), "r"(b[0]), "r"(b[1]));
}

// ---------------- Pass1: T = HS @ M via tf32 mma.sync ----------------------
// CTA tile 128(M) x 256(N), k-chunk 32, 8 warps (2x4), warp tile 64x64.
// smem per stage: A 128x36 fl + B 256x36 fl (row stride 36 = conflict-free pad)
#define P1_AS 0
#define P1_BS (128 * 36)
#define P1_STAGE (128 * 36 + 256 * 36)          // 13824 floats
#define P1_SMEM (2 * P1_STAGE * 4)              // 110592 bytes

__global__ __launch_bounds__(256, 1) void pass1_mma(const float* __restrict__ HS) {
    extern __shared__ float smem[];
    uint32_t sb = smem_u32(smem);
    int tid = threadIdx.x, wid = tid >> 5, lane = tid & 31;
    int wm = wid >> 2, wn = wid & 3;
    int lr = lane >> 2, lc = lane & 3;
    int m_base = blockIdx.y * 128;
    int n_base = blockIdx.x * 256;

    const float* Ag = HS + (size_t)m_base * HIDDEN;

    // prefetch helper: 3072 float4 per stage (A:1024, B:2048), 12 per thread
    auto prefetch = [&](int chunk, int stg) {
        int k0 = chunk * 32;
        uint32_t sA = sb + (stg * P1_STAGE + P1_AS) * 4;
        uint32_t sB = sb + (stg * P1_STAGE + P1_BS) * 4;
#pragma unroll
        for (int it = 0; it < 4; it++) {                 // A: 1024 f4
            int idx = tid + it * 256;
            int row = idx >> 3, seg = idx & 7;
            cp_async16(sA + (row * 36 + seg * 4) * 4,
                       Ag + (size_t)row * HIDDEN + k0 + seg * 4);
        }
#pragma unroll
        for (int it = 0; it < 8; it++) {                 // B: 2048 f4
            int idx = tid + it * 256;
            int row = idx >> 3, seg = idx & 7;
            cp_async16(sB + (row * 36 + seg * 4) * 4,
                       g_M + (size_t)(n_base + row) * HIDDEN + k0 + seg * 4);
        }
    };

    float acc[4][8][4];
#pragma unroll
    for (int i = 0; i < 4; i++)
#pragma unroll
        for (int j = 0; j < 8; j++)
#pragma unroll
            for (int t = 0; t < 4; t++) acc[i][j][t] = 0.0f;

    prefetch(0, 0);
    CP_COMMIT();

    for (int c = 0; c < 32; c++) {
        int stg = c & 1;
        if (c < 31) { prefetch(c + 1, stg ^ 1); CP_COMMIT(); CP_WAIT1(); }
        else        { CP_WAIT0(); }
        __syncthreads();
        const float* As = smem + stg * P1_STAGE + P1_AS;
        const float* Bs = smem + stg * P1_STAGE + P1_BS;
#pragma unroll
        for (int ks = 0; ks < 4; ks++) {
            int kk = ks * 8;
            uint32_t a[4][4], b[8][2];
#pragma unroll
            for (int mi = 0; mi < 4; mi++) {
                int r = wm * 64 + mi * 16 + lr;
                a[mi][0] = f2tf32(As[r * 36 + kk + lc]);
                a[mi][1] = f2tf32(As[(r + 8) * 36 + kk + lc]);
                a[mi][2] = f2tf32(As[r * 36 + kk + lc + 4]);
                a[mi][3] = f2tf32(As[(r + 8) * 36 + kk + lc + 4]);
            }
#pragma unroll
            for (int ni = 0; ni < 8; ni++) {
                int n = wn * 64 + ni * 8 + lr;
                b[ni][0] = f2tf32(Bs[n * 36 + kk + lc]);
                b[ni][1] = f2tf32(Bs[n * 36 + kk + lc + 4]);
            }
#pragma unroll
            for (int mi = 0; mi < 4; mi++)
#pragma unroll
                for (int ni = 0; ni < 8; ni++)
                    mma_tf32(acc[mi][ni], a[mi], b[ni]);
        }
        __syncthreads();
    }

    // epilogue: store acc (float2 per c0/c1 and c2/c3 pair)
#pragma unroll
    for (int mi = 0; mi < 4; mi++) {
        int r0 = m_base + wm * 64 + mi * 16 + lr;
#pragma unroll
        for (int ni = 0; ni < 8; ni++) {
            int col = n_base + wn * 64 + ni * 8 + lc * 2;
            *(float2*)&g_T[(size_t)r0 * HIDDEN + col] = make_float2(acc[mi][ni][0], acc[mi][ni][1]);
            *(float2*)&g_T[(size_t)(r0 + 8) * HIDDEN + col] = make_float2(acc[mi][ni][2], acc[mi][ni][3]);
        }
    }
}

// ---------------- Pass2: PA[b] = T[b] @ HS[b]^T / 128 via mma.sync ---------
// CTA per board: M=64, N=64, K=1024. 4 warps (2x2), warp tile 32x32.
__global__ __launch_bounds__(128) void pass2_mma(const float* __restrict__ HS,
                                                 float* __restrict__ PA) {
    __shared__ float Ts[2][64 * 36];
    __shared__ float Hs[2][64 * 36];
    int b = blockIdx.x;
    int tid = threadIdx.x, wid = tid >> 5, lane = tid & 31;
    int wm = wid >> 1, wn = wid & 1;
    int lr = lane >> 2, lc = lane & 3;

    const float* Tg = g_T + (size_t)b * 64 * HIDDEN;
    const float* Hg = HS + (size_t)b * 64 * HIDDEN;
    uint32_t sT0 = smem_u32(&Ts[0][0]);
    uint32_t sH0 = smem_u32(&Hs[0][0]);

    auto prefetch = [&](int chunk, int stg) {
        int k0 = chunk * 32;
        uint32_t sT = sT0 + stg * 64 * 36 * 4;
        uint32_t sH = sH0 + stg * 64 * 36 * 4;
#pragma unroll
        for (int it = 0; it < 4; it++) {                 // 512 f4 each array
            int idx = tid + it * 128;
            int row = idx >> 3, seg = idx & 7;
            cp_async16(sT + (row * 36 + seg * 4) * 4, Tg + (size_t)row * HIDDEN + k0 + seg * 4);
            cp_async16(sH + (row * 36 + seg * 4) * 4, Hg + (size_t)row * HIDDEN + k0 + seg * 4);
        }
    };

    float acc[2][4][4];
#pragma unroll
    for (int i = 0; i < 2; i++)
#pragma unroll
        for (int j = 0; j < 4; j++)
#pragma unroll
            for (int t = 0; t < 4; t++) acc[i][j][t] = 0.0f;

    prefetch(0, 0);
    CP_COMMIT();

    for (int c = 0; c < 32; c++) {
        int stg = c & 1;
        if (c < 31) { prefetch(c + 1, stg ^ 1); CP_COMMIT(); CP_WAIT1(); }
        else        { CP_WAIT0(); }
        __syncthreads();
        const float* As = Ts[stg];
        const float* Bs = Hs[stg];
#pragma unroll
        for (int ks = 0; ks < 4; ks++) {
            int kk = ks * 8;
            uint32_t a[2][4], bb[4][2];
#pragma unroll
            for (int mi = 0; mi < 2; mi++) {
                int r = wm * 32 + mi * 16 + lr;
                a[mi][0] = f2tf32(As[r * 36 + kk + lc]);
                a[mi][1] = f2tf32(As[(r + 8) * 36 + kk + lc]);
                a[mi][2] = f2tf32(As[r * 36 + kk + lc + 4]);
                a[mi][3] = f2tf32(As[(r + 8) * 36 + kk + lc + 4]);
            }
#pragma unroll
            for (int ni = 0; ni < 4; ni++) {
                int n = wn * 32 + ni * 8 + lr;
                bb[ni][0] = f2tf32(Bs[n * 36 + kk + lc]);
                bb[ni][1] = f2tf32(Bs[n * 36 + kk + lc + 4]);
            }
#pragma unroll
            for (int mi = 0; mi < 2; mi++)
#pragma unroll
                for (int ni = 0; ni < 4; ni++)
                    mma_tf32(acc[mi][ni], a[mi], bb[ni]);
        }
        __syncthreads();
    }

    const float s = 1.0f / 128.0f;
    float* pa = PA + (size_t)b * 4096;
#pragma unroll
    for (int mi = 0; mi < 2; mi++) {
        int r0 = wm * 32 + mi * 16 + lr;
#pragma unroll
        for (int ni = 0; ni < 4; ni++) {
            int col = wn * 32 + ni * 8 + lc * 2;
            *(float2*)&pa[r0 * 64 + col] = make_float2(acc[mi][ni][0] * s, acc[mi][ni][1] * s);
            *(float2*)&pa[(r0 + 8) * 64 + col] = make_float2(acc[mi][ni][2] * s, acc[mi][ni][3] * s);
        }
    }
}

// ---------------- colmap: 4-segment parallel build + ordered merge ---------
__global__ void build_colmap_seg(const float* __restrict__ pm) {
    int c = blockIdx.x * blockDim.x + threadIdx.x;
    int seg = blockIdx.y;
    if (c >= NCOLS) return;
    int r0 = seg * 1072, r1 = r0 + 1072;
    if (r1 > NROWS_PM) r1 = NROWS_PM;
    int n = 0;
    for (int r = r0; r < r1; r++) {
        if (pm[(size_t)r * NCOLS + c] != 0.0f) {
            if (n < 16) g_rows4[(seg * NCOLS + c) * 16 + n] = r;
            n++;
        }
    }
    g_cnt4[seg * NCOLS + c] = (n > 16) ? 16 : n;
}
__global__ void merge_colmap() {
    int c = blockIdx.x * blockDim.x + threadIdx.x;
    if (c >= NCOLS) return;
    int n = 0;
    for (int seg = 0; seg < 4; seg++) {
        int m = g_cnt4[seg * NCOLS + c];
        for (int t = 0; t < m && n < 16; t++)
            g_rows[c * 16 + n++] = g_rows4[(seg * NCOLS + c) * 16 + t];
    }
    g_cnt[c] = n;
}

// ---------------- g_M = Wk^T @ Wq (g_M[n][k] = (Wq^T Wk)[k][n]) ------------
__global__ __launch_bounds__(256) void gemm_tn_1024(
    const float* __restrict__ A, const float* __restrict__ B) {
    __shared__ float As[8][128];
    __shared__ float Bs[8][128];
    int bi = blockIdx.y, bj = blockIdx.x;
    int tid = threadIdx.x;
    int lrow = tid >> 5;
    int lcol = (tid & 31) * 4;
    int tx = tid & 15, ty = tid >> 4;
    const float* Ap = A + (size_t)lrow * HIDDEN + bi * 128 + lcol;
    const float* Bp = B + (size_t)lrow * HIDDEN + bj * 128 + lcol;
    float acc[8][8];
#pragma unroll
    for (int i = 0; i < 8; i++)
#pragma unroll
        for (int j = 0; j < 8; j++) acc[i][j] = 0.0f;
    for (int k0 = 0; k0 < HIDDEN; k0 += 8) {
        *(float4*)&As[lrow][lcol] = *(const float4*)(Ap + (size_t)k0 * HIDDEN);
        *(float4*)&Bs[lrow][lcol] = *(const float4*)(Bp + (size_t)k0 * HIDDEN);
        __syncthreads();
#pragma unroll
        for (int k = 0; k < 8; k++) {
            float a[8], b[8];
            *(float4*)&a[0] = *(float4*)&As[k][ty * 4];
            *(float4*)&a[4] = *(float4*)&As[k][64 + ty * 4];
            *(float4*)&b[0] = *(float4*)&Bs[k][tx * 4];
            *(float4*)&b[4] = *(float4*)&Bs[k][64 + tx * 4];
#pragma unroll
            for (int i = 0; i < 8; i++)
#pragma unroll
                for (int j = 0; j < 8; j++) acc[i][j] += a[i] * b[j];
        }
        __syncthreads();
    }
#pragma unroll
    for (int ih = 0; ih < 2; ih++)
#pragma unroll
        for (int i = 0; i < 4; i++) {
            int row = bi * 128 + ih * 64 + ty * 4 + i;
#pragma unroll
            for (int jh = 0; jh < 2; jh++) {
                float4 v = make_float4(acc[ih * 4 + i][jh * 4 + 0], acc[ih * 4 + i][jh * 4 + 1],
                                       acc[ih * 4 + i][jh * 4 + 2], acc[ih * 4 + i][jh * 4 + 3]);
                *(float4*)&g_M[(size_t)row * HIDDEN + bj * 128 + jh * 64 + tx * 4] = v;
            }
        }
}

// ---------------- Weff = (Wpo @ Wpk) rows 0..2 -----------------------------
__global__ void weff_kernel(const float* __restrict__ Wpo, const float* __restrict__ Wpk) {
    int i = blockIdx.x;
    int tid = threadIdx.x;
    float acc[4] = {0.f, 0.f, 0.f, 0.f};
    for (int c = 0; c < HIDDEN; c++) {
        float w = Wpo[i * HIDDEN + c];
        const float* row = Wpk + (size_t)c * HIDDEN;
#pragma unroll
        for (int j = 0; j < 4; j++) acc[j] += w * row[j * 256 + tid];
    }
#pragma unroll
    for (int j = 0; j < 4; j++) g_Weff[i * HIDDEN + j * 256 + tid] = acc[j];
}

// ---------------- promo offsets -------------------------------------------
__global__ void promo_kernel(const float* __restrict__ HS) {
    int b = blockIdx.x;
    int tid = threadIdx.x;
    int lane = tid & 31, w = tid >> 5;
    for (int p = w; p < 24; p += 8) {
        int i = p >> 3;
        int s = p & 7;
        const float* h = HS + ((size_t)b * 64 + 48 + s) * HIDDEN;
        const float* we = g_Weff + i * HIDDEN;
        float acc = 0.f;
        for (int d = lane; d < HIDDEN; d += 32) acc += h[d] * we[d];
#pragma unroll
        for (int o = 16; o; o >>= 1) acc += __shfl_xor_sync(0xFFFFFFFFu, acc, o);
        if (lane == 0) g_PO[b * 24 + i * 8 + s] = acc;
    }
}

// ---------------- final sparse gather --------------------------------------
__global__ void gather_kernel(float* __restrict__ PL, const float* __restrict__ PAfull) {
    int c = blockIdx.x * blockDim.x + threadIdx.x;
    int b = blockIdx.y;
    if (c >= NCOLS) return;
    const float* pa = PAfull + (size_t)b * 4096;
    int n = g_cnt[c];
    float v = 0.f;
    for (int t = 0; t < n; t++) {
        int r = g_rows[c * 16 + t];
        if (r < 4096) {
            v += pa[r] * 0.125f;
        } else {
            int u = r - 4096;
            int r8 = u / 24, rem = u % 24;
            int cc = rem / 3, ii = rem % 3;
            v += pa[(48 + r8) * 64 + 56 + cc] + 8.0f * g_PO[b * 24 + ii * 8 + cc];
        }
    }
    PL[(size_t)b * NCOLS + c] = v;
}

// ---------------- launcher -------------------------------------------------
extern "C" void kernel_launch(void* const* d_in, const int* in_sizes, int n_in,
                              void* d_out, int out_size) {
    const float* HS  = (const float*)d_in[0];
    const float* Wq  = (const float*)d_in[1];
    const float* Wk  = (const float*)d_in[2];
    const float* Wpk = (const float*)d_in[3];
    const float* Wpo = (const float*)d_in[4];
    const float* pm  = (const float*)d_in[5];
    int B = in_sizes[0] / (64 * HIDDEN);

    float* out = (float*)d_out;
    float* PL = out;
    float* PA = out + (size_t)B * NCOLS;

    cudaFuncSetAttribute(pass1_mma, cudaFuncAttributeMaxDynamicSharedMemorySize, P1_SMEM);

    build_colmap_seg<<<dim3((NCOLS + 255) / 256, 4), 256>>>(pm);
    merge_colmap<<<(NCOLS + 255) / 256, 256>>>();
    gemm_tn_1024<<<dim3(8, 8), 256>>>(Wk, Wq);      // g_M[n][k] = M[k][n]
    weff_kernel<<<3, 256>>>(Wpo, Wpk);
    pass1_mma<<<dim3(4, (B * 64) / 128), 256, P1_SMEM>>>(HS);
    pass2_mma<<<B, 128>>>(HS, PA);
    promo_kernel<<<B, 256>>>(HS);
    gather_kernel<<<dim3((NCOLS + 255) / 256, B), 256>>>(PL, PA);
}

// round 6
// speedup vs baseline: 1.1575x; 1.1575x over previous
#include <cuda_runtime.h>
#include <cstdint>

#define HIDDEN 1024
#define NCOLS 1858
#define NROWS_PM 4288
#define MAXB 2048
#define NSEG 16

// ---------------- scratch (device globals: allocation-free) ----------------
__device__ float g_T[(size_t)MAXB * 64 * HIDDEN];   // T = HS @ M (tf32-rounded)
__device__ float g_HS[(size_t)MAXB * 64 * HIDDEN];  // HS tf32-rounded
__device__ float g_M[HIDDEN * HIDDEN];              // g_M[n][k] = M[k][n] (tf32-rounded)
__device__ float g_Weff[3 * HIDDEN];
__device__ float g_PO[MAXB * 24];
__device__ int   g_cnt[NCOLS];
__device__ int   g_rows[NCOLS * 16];
__device__ int   g_cntS[NSEG * NCOLS];
__device__ int   g_rowsS[NSEG * NCOLS * 8];

// ---------------- PTX helpers (arch-agnostic: sm_80+ only) -----------------
__device__ __forceinline__ uint32_t smem_u32(const void* p) {
    uint32_t a;
    asm("{ .reg .u64 t; cvta.to.shared.u64 t, %1; cvt.u32.u64 %0, t; }" : "=r"(a) : "l"(p));
    return a;
}
__device__ __forceinline__ void cp_async16(uint32_t s, const void* g) {
    asm volatile("cp.async.cg.shared.global [%0], [%1], 16;" :: "r"(s), "l"(g));
}
#define CP_COMMIT() asm volatile("cp.async.commit_group;" ::: "memory")
#define CP_WAIT1() asm volatile("cp.async.wait_group 1;" ::: "memory")
#define CP_WAIT0() asm volatile("cp.async.wait_group 0;" ::: "memory")

__device__ __forceinline__ float f2tf32f(float x) {
    uint32_t r;
    asm("cvt.rna.tf32.f32 %0, %1;" : "=r"(r) : "f"(x));
    return __uint_as_float(r);
}
__device__ __forceinline__ void mma_tf32(float* c, const uint32_t* a, const uint32_t* b) {
    asm volatile(
        "mma.sync.aligned.m16n8k8.row.col.f32.tf32.tf32.f32 "
        "{%0,%1,%2,%3}, {%4,%5,%6,%7}, {%8,%9}, {%0,%1,%2,%3};"
        : "+f"(c[0]), "+f"(c[1]), "+f"(c[2]), "+f"(c[3])
        : "r"(a[0]), "r"(a[1]), "r"(a[2]), "r"(a[3]), "r"(b[0]), "r"(b[1]));
}

// ---------------- pre-round HS -> g_HS (tf32) ------------------------------
__global__ __launch_bounds__(256) void preround_hs(const float* __restrict__ HS, int n4) {
    int i = blockIdx.x * blockDim.x + threadIdx.x;
    if (i >= n4) return;
    float4 v = ((const float4*)HS)[i];
    v.x = f2tf32f(v.x); v.y = f2tf32f(v.y); v.z = f2tf32f(v.z); v.w = f2tf32f(v.w);
    ((float4*)g_HS)[i] = v;
}

// ---------------- Pass1: T = g_HS @ g_M via tf32 mma.sync ------------------
// CTA tile 128(M) x 256(N), k-chunk 32, 8 warps (2x4), warp tile 64x64.
#define P1_AS 0
#define P1_BS (128 * 36)
#define P1_STAGE (128 * 36 + 256 * 36)
#define P1_SMEM (2 * P1_STAGE * 4)

__global__ __launch_bounds__(256, 1) void pass1_mma() {
    extern __shared__ float smem[];
    uint32_t sb = smem_u32(smem);
    int tid = threadIdx.x, wid = tid >> 5, lane = tid & 31;
    int wm = wid >> 2, wn = wid & 3;
    int lr = lane >> 2, lc = lane & 3;
    int m_base = blockIdx.y * 128;
    int n_base = blockIdx.x * 256;

    const float* Ag = g_HS + (size_t)m_base * HIDDEN;

    auto prefetch = [&](int chunk, int stg) {
        int k0 = chunk * 32;
        uint32_t sA = sb + (stg * P1_STAGE + P1_AS) * 4;
        uint32_t sB = sb + (stg * P1_STAGE + P1_BS) * 4;
#pragma unroll
        for (int it = 0; it < 4; it++) {
            int idx = tid + it * 256;
            int row = idx >> 3, seg = idx & 7;
            cp_async16(sA + (row * 36 + seg * 4) * 4,
                       Ag + (size_t)row * HIDDEN + k0 + seg * 4);
        }
#pragma unroll
        for (int it = 0; it < 8; it++) {
            int idx = tid + it * 256;
            int row = idx >> 3, seg = idx & 7;
            cp_async16(sB + (row * 36 + seg * 4) * 4,
                       g_M + (size_t)(n_base + row) * HIDDEN + k0 + seg * 4);
        }
    };

    float acc[4][8][4];
#pragma unroll
    for (int i = 0; i < 4; i++)
#pragma unroll
        for (int j = 0; j < 8; j++)
#pragma unroll
            for (int t = 0; t < 4; t++) acc[i][j][t] = 0.0f;

    prefetch(0, 0);
    CP_COMMIT();

    for (int c = 0; c < 32; c++) {
        int stg = c & 1;
        if (c < 31) { prefetch(c + 1, stg ^ 1); CP_COMMIT(); CP_WAIT1(); }
        else        { CP_WAIT0(); }
        __syncthreads();
        const uint32_t* As = (const uint32_t*)(smem + stg * P1_STAGE + P1_AS);
        const uint32_t* Bs = (const uint32_t*)(smem + stg * P1_STAGE + P1_BS);
#pragma unroll
        for (int ks = 0; ks < 4; ks++) {
            int kk = ks * 8;
            uint32_t a[4][4], b[8][2];
#pragma unroll
            for (int mi = 0; mi < 4; mi++) {
                int r = wm * 64 + mi * 16 + lr;
                a[mi][0] = As[r * 36 + kk + lc];
                a[mi][1] = As[(r + 8) * 36 + kk + lc];
                a[mi][2] = As[r * 36 + kk + lc + 4];
                a[mi][3] = As[(r + 8) * 36 + kk + lc + 4];
            }
#pragma unroll
            for (int ni = 0; ni < 8; ni++) {
                int n = wn * 64 + ni * 8 + lr;
                b[ni][0] = Bs[n * 36 + kk + lc];
                b[ni][1] = Bs[n * 36 + kk + lc + 4];
            }
#pragma unroll
            for (int mi = 0; mi < 4; mi++)
#pragma unroll
                for (int ni = 0; ni < 8; ni++)
                    mma_tf32(acc[mi][ni], a[mi], b[ni]);
        }
        __syncthreads();
    }

    // epilogue: store tf32-rounded (pass2 consumes as raw tf32 bits)
#pragma unroll
    for (int mi = 0; mi < 4; mi++) {
        int r0 = m_base + wm * 64 + mi * 16 + lr;
#pragma unroll
        for (int ni = 0; ni < 8; ni++) {
            int col = n_base + wn * 64 + ni * 8 + lc * 2;
            *(float2*)&g_T[(size_t)r0 * HIDDEN + col] =
                make_float2(f2tf32f(acc[mi][ni][0]), f2tf32f(acc[mi][ni][1]));
            *(float2*)&g_T[(size_t)(r0 + 8) * HIDDEN + col] =
                make_float2(f2tf32f(acc[mi][ni][2]), f2tf32f(acc[mi][ni][3]));
        }
    }
}

// ---------------- Pass2: PA[b] = T[b] @ g_HS[b]^T / 128 --------------------
__global__ __launch_bounds__(128) void pass2_mma(float* __restrict__ PA) {
    __shared__ float Ts[2][64 * 36];
    __shared__ float Hs[2][64 * 36];
    int b = blockIdx.x;
    int tid = threadIdx.x, wid = tid >> 5, lane = tid & 31;
    int wm = wid >> 1, wn = wid & 1;
    int lr = lane >> 2, lc = lane & 3;

    const float* Tg = g_T + (size_t)b * 64 * HIDDEN;
    const float* Hg = g_HS + (size_t)b * 64 * HIDDEN;
    uint32_t sT0 = smem_u32(&Ts[0][0]);
    uint32_t sH0 = smem_u32(&Hs[0][0]);

    auto prefetch = [&](int chunk, int stg) {
        int k0 = chunk * 32;
        uint32_t sT = sT0 + stg * 64 * 36 * 4;
        uint32_t sH = sH0 + stg * 64 * 36 * 4;
#pragma unroll
        for (int it = 0; it < 4; it++) {
            int idx = tid + it * 128;
            int row = idx >> 3, seg = idx & 7;
            cp_async16(sT + (row * 36 + seg * 4) * 4, Tg + (size_t)row * HIDDEN + k0 + seg * 4);
            cp_async16(sH + (row * 36 + seg * 4) * 4, Hg + (size_t)row * HIDDEN + k0 + seg * 4);
        }
    };

    float acc[2][4][4];
#pragma unroll
    for (int i = 0; i < 2; i++)
#pragma unroll
        for (int j = 0; j < 4; j++)
#pragma unroll
            for (int t = 0; t < 4; t++) acc[i][j][t] = 0.0f;

    prefetch(0, 0);
    CP_COMMIT();

    for (int c = 0; c < 32; c++) {
        int stg = c & 1;
        if (c < 31) { prefetch(c + 1, stg ^ 1); CP_COMMIT(); CP_WAIT1(); }
        else        { CP_WAIT0(); }
        __syncthreads();
        const uint32_t* As = (const uint32_t*)Ts[stg];
        const uint32_t* Bs = (const uint32_t*)Hs[stg];
#pragma unroll
        for (int ks = 0; ks < 4; ks++) {
            int kk = ks * 8;
            uint32_t a[2][4], bb[4][2];
#pragma unroll
            for (int mi = 0; mi < 2; mi++) {
                int r = wm * 32 + mi * 16 + lr;
                a[mi][0] = As[r * 36 + kk + lc];
                a[mi][1] = As[(r + 8) * 36 + kk + lc];
                a[mi][2] = As[r * 36 + kk + lc + 4];
                a[mi][3] = As[(r + 8) * 36 + kk + lc + 4];
            }
#pragma unroll
            for (int ni = 0; ni < 4; ni++) {
                int n = wn * 32 + ni * 8 + lr;
                bb[ni][0] = Bs[n * 36 + kk + lc];
                bb[ni][1] = Bs[n * 36 + kk + lc + 4];
            }
#pragma unroll
            for (int mi = 0; mi < 2; mi++)
#pragma unroll
                for (int ni = 0; ni < 4; ni++)
                    mma_tf32(acc[mi][ni], a[mi], bb[ni]);
        }
        __syncthreads();
    }

    const float s = 1.0f / 128.0f;
    float* pa = PA + (size_t)b * 4096;
#pragma unroll
    for (int mi = 0; mi < 2; mi++) {
        int r0 = wm * 32 + mi * 16 + lr;
#pragma unroll
        for (int ni = 0; ni < 4; ni++) {
            int col = wn * 32 + ni * 8 + lc * 2;
            *(float2*)&pa[r0 * 64 + col] = make_float2(acc[mi][ni][0] * s, acc[mi][ni][1] * s);
            *(float2*)&pa[(r0 + 8) * 64 + col] = make_float2(acc[mi][ni][2] * s, acc[mi][ni][3] * s);
        }
    }
}

// ---------------- colmap: 16-segment parallel build + ordered merge --------
__global__ void build_colmap_seg(const float* __restrict__ pm) {
    int c = blockIdx.x * blockDim.x + threadIdx.x;
    int seg = blockIdx.y;
    if (c >= NCOLS) return;
    int r0 = seg * 268, r1 = r0 + 268;
    if (r1 > NROWS_PM) r1 = NROWS_PM;
    int n = 0;
    for (int r = r0; r < r1; r++) {
        if (pm[(size_t)r * NCOLS + c] != 0.0f) {
            if (n < 8) g_rowsS[(seg * NCOLS + c) * 8 + n] = r;
            n++;
        }
    }
    g_cntS[seg * NCOLS + c] = (n > 8) ? 8 : n;
}
__global__ void merge_colmap() {
    int c = blockIdx.x * blockDim.x + threadIdx.x;
    if (c >= NCOLS) return;
    int n = 0;
    for (int seg = 0; seg < NSEG; seg++) {
        int m = g_cntS[seg * NCOLS + c];
        for (int t = 0; t < m && n < 16; t++)
            g_rows[c * 16 + n++] = g_rowsS[(seg * NCOLS + c) * 8 + t];
    }
    g_cnt[c] = n;
}

// ---------------- g_M = Wk^T @ Wq (tf32-rounded) ---------------------------
__global__ __launch_bounds__(256) void gemm_tn_1024(
    const float* __restrict__ A, const float* __restrict__ B) {
    __shared__ float As[8][128];
    __shared__ float Bs[8][128];
    int bi = blockIdx.y, bj = blockIdx.x;
    int tid = threadIdx.x;
    int lrow = tid >> 5;
    int lcol = (tid & 31) * 4;
    int tx = tid & 15, ty = tid >> 4;
    const float* Ap = A + (size_t)lrow * HIDDEN + bi * 128 + lcol;
    const float* Bp = B + (size_t)lrow * HIDDEN + bj * 128 + lcol;
    float acc[8][8];
#pragma unroll
    for (int i = 0; i < 8; i++)
#pragma unroll
        for (int j = 0; j < 8; j++) acc[i][j] = 0.0f;
    for (int k0 = 0; k0 < HIDDEN; k0 += 8) {
        *(float4*)&As[lrow][lcol] = *(const float4*)(Ap + (size_t)k0 * HIDDEN);
        *(float4*)&Bs[lrow][lcol] = *(const float4*)(Bp + (size_t)k0 * HIDDEN);
        __syncthreads();
#pragma unroll
        for (int k = 0; k < 8; k++) {
            float a[8], b[8];
            *(float4*)&a[0] = *(float4*)&As[k][ty * 4];
            *(float4*)&a[4] = *(float4*)&As[k][64 + ty * 4];
            *(float4*)&b[0] = *(float4*)&Bs[k][tx * 4];
            *(float4*)&b[4] = *(float4*)&Bs[k][64 + tx * 4];
#pragma unroll
            for (int i = 0; i < 8; i++)
#pragma unroll
                for (int j = 0; j < 8; j++) acc[i][j] += a[i] * b[j];
        }
        __syncthreads();
    }
#pragma unroll
    for (int ih = 0; ih < 2; ih++)
#pragma unroll
        for (int i = 0; i < 4; i++) {
            int row = bi * 128 + ih * 64 + ty * 4 + i;
#pragma unroll
            for (int jh = 0; jh < 2; jh++) {
                float4 v = make_float4(f2tf32f(acc[ih * 4 + i][jh * 4 + 0]),
                                       f2tf32f(acc[ih * 4 + i][jh * 4 + 1]),
                                       f2tf32f(acc[ih * 4 + i][jh * 4 + 2]),
                                       f2tf32f(acc[ih * 4 + i][jh * 4 + 3]));
                *(float4*)&g_M[(size_t)row * HIDDEN + bj * 128 + jh * 64 + tx * 4] = v;
            }
        }
}

// ---------------- Weff: zero + 48-block partial accumulate -----------------
__global__ void weff_zero() {
    int i = blockIdx.x * blockDim.x + threadIdx.x;
    if (i < 3 * HIDDEN) g_Weff[i] = 0.0f;
}
__global__ void weff_partial(const float* __restrict__ Wpo, const float* __restrict__ Wpk) {
    int i = blockIdx.x;              // 0..2
    int seg = blockIdx.y;            // 0..15
    int tid = threadIdx.x;           // 256
    int c0 = seg * 64;
    float acc[4] = {0.f, 0.f, 0.f, 0.f};
    for (int c = c0; c < c0 + 64; c++) {
        float w = Wpo[i * HIDDEN + c];
        const float* row = Wpk + (size_t)c * HIDDEN;
#pragma unroll
        for (int j = 0; j < 4; j++) acc[j] += w * row[j * 256 + tid];
    }
#pragma unroll
    for (int j = 0; j < 4; j++) atomicAdd(&g_Weff[i * HIDDEN + j * 256 + tid], acc[j]);
}

// ---------------- promo offsets (full-precision HS) ------------------------
__global__ void promo_kernel(const float* __restrict__ HS) {
    int b = blockIdx.x;
    int tid = threadIdx.x;
    int lane = tid & 31, w = tid >> 5;
    for (int p = w; p < 24; p += 8) {
        int i = p >> 3;
        int s = p & 7;
        const float* h = HS + ((size_t)b * 64 + 48 + s) * HIDDEN;
        const float* we = g_Weff + i * HIDDEN;
        float acc = 0.f;
        for (int d = lane; d < HIDDEN; d += 32) acc += h[d] * we[d];
#pragma unroll
        for (int o = 16; o; o >>= 1) acc += __shfl_xor_sync(0xFFFFFFFFu, acc, o);
        if (lane == 0) g_PO[b * 24 + i * 8 + s] = acc;
    }
}

// ---------------- final sparse gather --------------------------------------
__global__ void gather_kernel(float* __restrict__ PL, const float* __restrict__ PAfull) {
    int c = blockIdx.x * blockDim.x + threadIdx.x;
    int b = blockIdx.y;
    if (c >= NCOLS) return;
    const float* pa = PAfull + (size_t)b * 4096;
    int n = g_cnt[c];
    float v = 0.f;
    for (int t = 0; t < n; t++) {
        int r = g_rows[c * 16 + t];
        if (r < 4096) {
            v += pa[r] * 0.125f;
        } else {
            int u = r - 4096;
            int r8 = u / 24, rem = u % 24;
            int cc = rem / 3, ii = rem % 3;
            v += pa[(48 + r8) * 64 + 56 + cc] + 8.0f * g_PO[b * 24 + ii * 8 + cc];
        }
    }
    PL[(size_t)b * NCOLS + c] = v;
}

// ---------------- launcher -------------------------------------------------
extern "C" void kernel_launch(void* const* d_in, const int* in_sizes, int n_in,
                              void* d_out, int out_size) {
    const float* HS  = (const float*)d_in[0];
    const float* Wq  = (const float*)d_in[1];
    const float* Wk  = (const float*)d_in[2];
    const float* Wpk = (const float*)d_in[3];
    const float* Wpo = (const float*)d_in[4];
    const float* pm  = (const float*)d_in[5];
    int B = in_sizes[0] / (64 * HIDDEN);

    float* out = (float*)d_out;
    float* PL = out;
    float* PA = out + (size_t)B * NCOLS;

    cudaFuncSetAttribute(pass1_mma, cudaFuncAttributeMaxDynamicSharedMemorySize, P1_SMEM);

    int n4 = (B * 64 * HIDDEN) / 4;
    preround_hs<<<(n4 + 255) / 256, 256>>>(HS, n4);
    build_colmap_seg<<<dim3((NCOLS + 255) / 256, NSEG), 256>>>(pm);
    merge_colmap<<<(NCOLS + 255) / 256, 256>>>();
    gemm_tn_1024<<<dim3(8, 8), 256>>>(Wk, Wq);
    weff_zero<<<12, 256>>>();
    weff_partial<<<dim3(3, 16), 256>>>(Wpo, Wpk);
    pass1_mma<<<dim3(4, (B * 64) / 128), 256, P1_SMEM>>>();
    pass2_mma<<<B, 128>>>(PA);
    promo_kernel<<<B, 256>>>(HS);
    gather_kernel<<<dim3((NCOLS + 255) / 256, B), 256>>>(PL, PA);
}